// round 11
// baseline (speedup 1.0000x reference)
#include <cuda_runtime.h>
#include <cstdint>

#define BATCH   4096
#define SEQ     32
#define DIM     256
#define VOCAB   50257
#define NALIVE  100

// 512 ctx blocks (8 rows each, warp-per-row) interleaved 1-per-25 among
// 12288 fill blocks. Total 12800 blocks.
#define NZB     12288
#define NBTOT   12800
#define TOTAL4  51463168   // BATCH*VOCAB/4

// Scratch: compacted nonzero activations per row (empty in practice).
__device__ float g_val[BATCH * NALIVE];
__device__ int   g_idx[BATCH * NALIVE];
__device__ int   g_cnt[BATCH];

__device__ __forceinline__ float warp_sum(float v) {
    #pragma unroll
    for (int off = 16; off > 0; off >>= 1)
        v += __shfl_xor_sync(0xFFFFFFFFu, v, off);
    return v;
}
__device__ __forceinline__ float warp_max(float v) {
    #pragma unroll
    for (int off = 16; off > 0; off >>= 1)
        v = fmaxf(v, __shfl_xor_sync(0xFFFFFFFFu, v, off));
    return v;
}

__global__ __launch_bounds__(256)
void fused_fill_ctx_kernel(const int*   __restrict__ tok,
                           const float* __restrict__ te,
                           const float* __restrict__ pe,
                           const float* __restrict__ q,
                           const float* __restrict__ pos,
                           float*       __restrict__ out) {
    const int bid = blockIdx.x;
    const int tid = threadIdx.x;            // 0..255

    if (bid % 25 != 0) {
        // ---------------- zero-fill role (12288 blocks) ----------------
        const int zid = bid - (bid / 25 + 1);            // 0..12287
        const float4 z = make_float4(0.f, 0.f, 0.f, 0.f);
        float4* __restrict__ o4 = (float4*)out;
        const long stride = (long)NZB * 256;
        for (long i = (long)zid * 256 + tid; i < (long)TOTAL4; i += stride)
            __stcs(o4 + i, z);
        return;
    }

    // -------- ctx role: warp-per-row, 8 rows per block, no block syncs -----
    const int lane = tid & 31;
    const int wid  = tid >> 5;                           // 0..7
    const int b    = (bid / 25) * 8 + wid;               // this warp's row

    // Per-lane state: token for seq position `lane`, q slice, later context.
    const int   mytok = tok[b * SEQ + lane];
    float qr[8];
    #pragma unroll
    for (int i = 0; i < 8; i++) qr[i] = __ldg(q + lane + 32 * i);

    // Phase B: attention scores. Iteration s computes score_s cooperatively;
    // lane s keeps it. embeds read straight from global (te rows go hot in L2).
    float score = 0.f;
    #pragma unroll 4
    for (int s = 0; s < SEQ; s++) {
        const int ts = __shfl_sync(0xFFFFFFFFu, mytok, s);
        const float* __restrict__ trow = te + (size_t)ts * DIM;
        const float* __restrict__ prow = pe + s * DIM;
        float p = 0.f;
        #pragma unroll
        for (int i = 0; i < 8; i++) {
            const int d = lane + 32 * i;
            p = fmaf(__ldg(trow + d) + __ldg(prow + d), qr[i], p);
        }
        p = warp_sum(p);
        if (lane == s) score = p * (1.0f / 16.0f);       // / sqrt(256)
    }

    // Phase C: softmax across lanes (lane s holds w_s).
    {
        const float mx = warp_max(score);
        const float e  = expf(score - mx);
        const float sm = warp_sum(e);
        score = e / sm;                                  // reuse as weight
    }

    // Phase D: context (8 dims per lane), rereading embeds (L2/L1-hot).
    float c[8] = {0.f, 0.f, 0.f, 0.f, 0.f, 0.f, 0.f, 0.f};
    #pragma unroll 4
    for (int s = 0; s < SEQ; s++) {
        const float ws = __shfl_sync(0xFFFFFFFFu, score, s);
        const int   ts = __shfl_sync(0xFFFFFFFFu, mytok, s);
        const float* __restrict__ trow = te + (size_t)ts * DIM;
        const float* __restrict__ prow = pe + s * DIM;
        #pragma unroll
        for (int i = 0; i < 8; i++) {
            const int d = lane + 32 * i;
            c[i] = fmaf(ws, __ldg(trow + d) + __ldg(prow + d), c[i]);
        }
    }

    // Phase E: RBF distances to 100 positions; lane (j&31) keeps d2 for
    // chunk k = j>>5 (compile-time k avoids local-memory indexing).
    const float FINF = __int_as_float(0x7f800000);
    float a[4] = {FINF, FINF, FINF, FINF};
    #pragma unroll
    for (int k = 0; k < 4; k++) {
        const int jmax = (k == 3) ? 4 : 32;              // 100 = 3*32 + 4
        for (int jj = 0; jj < jmax; jj++) {
            const int j = k * 32 + jj;
            const float* __restrict__ posr = pos + j * DIM;
            float p = 0.f;
            #pragma unroll
            for (int i = 0; i < 8; i++) {
                const float df = c[i] - __ldg(posr + lane + 32 * i);
                p = fmaf(df, df, p);
            }
            p = warp_sum(p);
            if (lane == jj) a[k] = p;
        }
    }
    #pragma unroll
    for (int k = 0; k < 4; k++) a[k] = expf(-2.0f * a[k]);  // exp(-inf)=0 pads

    // Phase F: normalize + warp-local compaction into global scratch.
    const float sum   = warp_sum(a[0] + a[1] + a[2] + a[3]);
    const float denom = sum + 1e-8f;
    int cnt = 0;
    #pragma unroll
    for (int k = 0; k < 4; k++) {
        const int j = k * 32 + lane;
        const float act = a[k] / denom;
        const bool nz = (j < NALIVE) && (act != 0.0f);
        const unsigned m = __ballot_sync(0xFFFFFFFFu, nz);
        const int pre = __popc(m & ((1u << lane) - 1u));
        if (nz) {
            g_val[b * NALIVE + cnt + pre] = act;
            g_idx[b * NALIVE + cnt + pre] = j;
        }
        cnt += __popc(m);
    }
    if (lane == 0) g_cnt[b] = cnt;
}

// Sparse fixup: 16 blocks, each checks 256 rows IN PARALLEL (one load round),
// exits immediately when all counts are zero (the common case, ~4 us).
__global__ __launch_bounds__(256)
void fixup_kernel(const float* __restrict__ W, float* __restrict__ out) {
    __shared__ int   s_cnt_arr[256];
    __shared__ float s_val[NALIVE];
    __shared__ int   s_idx[NALIVE];

    const int tid = threadIdx.x;
    const int b0  = blockIdx.x * 256;

    const int mycnt = g_cnt[b0 + tid];
    s_cnt_arr[tid] = mycnt;
    if (__syncthreads_count(mycnt != 0) == 0) return;   // all-zero: exit

    for (int r = 0; r < 256; r++) {
        const int cnt = s_cnt_arr[r];
        if (cnt == 0) continue;
        const int b = b0 + r;

        if (tid < cnt) {
            s_val[tid] = g_val[b * NALIVE + tid];
            s_idx[tid] = g_idx[b * NALIVE + tid];
        }
        __syncthreads();

        float* __restrict__ orow = out + (size_t)b * VOCAB;
        for (int v = tid; v < VOCAB; v += 256) {
            float acc = 0.f;
            for (int k = 0; k < cnt; k++)
                acc = fmaf(s_val[k], W[(size_t)s_idx[k] * VOCAB + v], acc);
            orow[v] = acc;
        }
        __syncthreads();
    }
}

extern "C" void kernel_launch(void* const* d_in, const int* in_sizes, int n_in,
                              void* d_out, int out_size) {
    const int*   tok = (const int*)  d_in[0];   // [B, S]
    const float* te  = (const float*)d_in[1];   // [V, D]
    const float* pe  = (const float*)d_in[2];   // [S, D]
    const float* q   = (const float*)d_in[3];   // [D]
    const float* pos = (const float*)d_in[4];   // [N, D]
    const float* W   = (const float*)d_in[5];   // [N, V]
    float* out = (float*)d_out;                 // [B, V]

    fused_fill_ctx_kernel<<<NBTOT, 256>>>(tok, te, pe, q, pos, out);
    fixup_kernel<<<16, 256>>>(W, out);
}

// round 12
// speedup vs baseline: 1.3987x; 1.3987x over previous
#include <cuda_runtime.h>
#include <cstdint>

#define BATCH   4096
#define SEQ     32
#define DIM     256
#define VOCAB   50257
#define NALIVE  100

// Fused grid: every 5th block is a ctx block (4096), rest are fill (16384).
#define NBTOT   20480
#define NZB     16384
#define TOTAL4  51463168   // BATCH*VOCAB/4

// Scratch: compacted nonzero activations per row (empty in practice).
__device__ float g_val[BATCH * NALIVE];
__device__ int   g_idx[BATCH * NALIVE];
__device__ int   g_cnt[BATCH];

__device__ __forceinline__ float warp_sum(float v) {
    #pragma unroll
    for (int off = 16; off > 0; off >>= 1)
        v += __shfl_xor_sync(0xFFFFFFFFu, v, off);
    return v;
}
__device__ __forceinline__ float warp_max(float v) {
    #pragma unroll
    for (int off = 16; off > 0; off >>= 1)
        v = fmaxf(v, __shfl_xor_sync(0xFFFFFFFFu, v, off));
    return v;
}

// Low-smem (~2.6KB) + low-reg kernel: __launch_bounds__(256, 8) forces
// regs<=32 so ALL blocks (especially the 16384 fill blocks) get 8 blocks/SM
// (64 warps) instead of the 6 that 40 regs / 33KB smem allowed before.
__global__ __launch_bounds__(256, 8)
void fused_fill_ctx_kernel(const int*   __restrict__ tok,
                           const float* __restrict__ te,
                           const float* __restrict__ pe,
                           const float* __restrict__ q,
                           const float* __restrict__ pos,
                           float*       __restrict__ out) {
    const int bid = blockIdx.x;
    const int tid = threadIdx.x;            // 0..255

    if ((bid % 5) != 0) {
        // ---------------- zero-fill role (16384 blocks) ----------------
        const int zid = bid - (bid / 5 + 1);             // 0..16383
        const float4 z = make_float4(0.f, 0.f, 0.f, 0.f);
        float4* __restrict__ o4 = (float4*)out;
        const long stride = (long)NZB * 256;
        for (long i = (long)zid * 256 + tid; i < (long)TOTAL4; i += stride)
            __stcs(o4 + i, z);
        return;
    }

    // ---------------- ctx role (4096 blocks, b = bid/5) ----------------
    // No embed staging: te rows are read twice from L2 (hot after 1st touch).
    const int b = bid / 5;

    __shared__ float s_q[DIM];        // 1 KB
    __shared__ float s_ctx[DIM];      // 1 KB
    __shared__ float s_score[SEQ];
    __shared__ float s_w[SEQ];
    __shared__ float s_act[NALIVE];
    __shared__ int   s_tok[SEQ];

    const int lane = tid & 31;
    const int wid  = tid >> 5;             // 0..7

    s_q[tid] = q[tid];
    if (tid < SEQ) s_tok[tid] = tok[b * SEQ + tid];
    __syncthreads();

    // Phase B: attention scores, embeds read from global/L2 on the fly.
    // Warp w handles s = w, w+8, w+16, w+24.
    #pragma unroll
    for (int s = wid; s < SEQ; s += 8) {
        const float* __restrict__ trow = te + (size_t)s_tok[s] * DIM;
        const float* __restrict__ prow = pe + s * DIM;
        float p = 0.f;
        #pragma unroll
        for (int i = 0; i < 8; i++) {
            int d = lane + 32 * i;
            p = fmaf(__ldg(trow + d) + __ldg(prow + d), s_q[d], p);
        }
        p = warp_sum(p);
        if (lane == 0) s_score[s] = p * (1.0f / 16.0f);   // / sqrt(256)
    }
    __syncthreads();

    // Phase C: softmax over S=32 (warp 0, one score per lane)
    if (wid == 0) {
        float sc = s_score[lane];
        float m  = warp_max(sc);
        float e  = expf(sc - m);
        float s  = warp_sum(e);
        s_w[lane] = e / s;
    }
    __syncthreads();

    // Phase D: context[d] = sum_s w[s] * (te[tok[s]][d] + pe[s][d])  (L2-warm)
    {
        const int d = tid;
        float c = 0.f;
        #pragma unroll
        for (int s = 0; s < SEQ; s++) {
            float e = __ldg(te + (size_t)s_tok[s] * DIM + d) + __ldg(pe + s * DIM + d);
            c = fmaf(s_w[s], e, c);
        }
        s_ctx[d] = c;
    }
    __syncthreads();

    // Phase E: RBF distances to 100 positions (warp w handles j = w, w+8, ...)
    for (int j = wid; j < NALIVE; j += 8) {
        float p = 0.f;
        #pragma unroll
        for (int i = 0; i < 8; i++) {
            int d = lane + 32 * i;
            float df = s_ctx[d] - __ldg(pos + j * DIM + d);
            p = fmaf(df, df, p);
        }
        p = warp_sum(p);
        if (lane == 0) s_act[j] = expf(-2.0f * p);   // exp(-d2 / (2*0.5^2))
    }
    __syncthreads();

    // Phase F: normalize + compact nonzeros (warp 0)
    if (wid == 0) {
        float sum = 0.f;
        for (int j = lane; j < NALIVE; j += 32) sum += s_act[j];
        sum = warp_sum(sum);
        const float denom = sum + 1e-8f;

        int cnt = 0;
        #pragma unroll
        for (int base = 0; base < NALIVE; base += 32) {
            int j = base + lane;
            float a = 0.f;
            bool nz = false;
            if (j < NALIVE) {
                a  = s_act[j] / denom;
                nz = (a != 0.0f);
            }
            unsigned m = __ballot_sync(0xFFFFFFFFu, nz);
            int pre = __popc(m & ((1u << lane) - 1u));
            if (nz) {
                g_val[b * NALIVE + cnt + pre] = a;
                g_idx[b * NALIVE + cnt + pre] = j;
            }
            cnt += __popc(m);
        }
        if (lane == 0) g_cnt[b] = cnt;
    }
}

// Sparse fixup: 16 blocks, each checks 256 rows IN PARALLEL (one load round),
// exits immediately when all counts are zero (the common case, ~4 us).
__global__ __launch_bounds__(256)
void fixup_kernel(const float* __restrict__ W, float* __restrict__ out) {
    __shared__ int   s_cnt_arr[256];
    __shared__ float s_val[NALIVE];
    __shared__ int   s_idx[NALIVE];

    const int tid = threadIdx.x;
    const int b0  = blockIdx.x * 256;

    const int mycnt = g_cnt[b0 + tid];
    s_cnt_arr[tid] = mycnt;
    if (__syncthreads_count(mycnt != 0) == 0) return;   // all-zero: exit

    for (int r = 0; r < 256; r++) {
        const int cnt = s_cnt_arr[r];
        if (cnt == 0) continue;
        const int b = b0 + r;

        if (tid < cnt) {
            s_val[tid] = g_val[b * NALIVE + tid];
            s_idx[tid] = g_idx[b * NALIVE + tid];
        }
        __syncthreads();

        float* __restrict__ orow = out + (size_t)b * VOCAB;
        for (int v = tid; v < VOCAB; v += 256) {
            float acc = 0.f;
            for (int k = 0; k < cnt; k++)
                acc = fmaf(s_val[k], W[(size_t)s_idx[k] * VOCAB + v], acc);
            orow[v] = acc;
        }
        __syncthreads();
    }
}

extern "C" void kernel_launch(void* const* d_in, const int* in_sizes, int n_in,
                              void* d_out, int out_size) {
    const int*   tok = (const int*)  d_in[0];   // [B, S]
    const float* te  = (const float*)d_in[1];   // [V, D]
    const float* pe  = (const float*)d_in[2];   // [S, D]
    const float* q   = (const float*)d_in[3];   // [D]
    const float* pos = (const float*)d_in[4];   // [N, D]
    const float* W   = (const float*)d_in[5];   // [N, V]
    float* out = (float*)d_out;                 // [B, V]

    fused_fill_ctx_kernel<<<NBTOT, 256>>>(tok, te, pe, q, pos, out);
    fixup_kernel<<<16, 256>>>(W, out);
}